// round 5
// baseline (speedup 1.0000x reference)
#include <cuda_runtime.h>
#include <cuda_bf16.h>

// JointBilateral upsample, S=4, K=5. One thread = 4 horizontal output pixels:
// output row 4p+s, cols 4q..4q+3. The 4 threads sharing (p,q) reuse the same
// tap point (4p+1, 4q+1) via cache. s is warp-uniform -> the second-row-tap
// path (s==3) is a uniform branch in 1/4 of warps.
//
// e(tap) = exp(-0.125*||g_tap - g_ctr||^2) * exp(-0.005*((i-2)^2+(j-2)^2))
// out = sum(e * wgt[4-i][4-j] * x_tap) / sum(e)

#define CH  (512 * 512)
#define E1  0.9950124791926823f   /* exp(-0.005) */
#define E4  0.9801986733067553f   /* exp(-0.020) */

__global__ void __launch_bounds__(256) jb_kernel(
    const float* __restrict__ x,
    const float* __restrict__ g,
    const float* __restrict__ wgt,
    float* __restrict__ out)
{
    int idx = blockIdx.x * 256 + threadIdx.x;   // 262144 threads
    int q = idx & 127;
    int s = (idx >> 7) & 3;      // warp-uniform
    int p = (idx >> 9) & 127;
    int b = idx >> 16;

    const float* gb = g + (size_t)b * 3 * CH;
    const float* xb = x + b * (128 * 128);

    bool col2 = (q < 127);
    int dq = col2 ? 4 : 0;
    int cq = col2 ? 1 : 0;

    int o00 = (4 * p + 1) * 512 + (4 * q + 1);
    int hrow = (4 * p + s) * 512 + 4 * q;

    // ---- front-loaded: centers, first tap, col tap, x ----
    float4 c0 = *(const float4*)(gb + hrow);
    float4 c1 = *(const float4*)(gb + CH + hrow);
    float4 c2 = *(const float4*)(gb + 2 * CH + hrow);

    float t0 = gb[o00];
    float t1 = gb[o00 + CH];
    float t2 = gb[o00 + 2 * CH];
    float u0 = gb[o00 + dq];
    float u1 = gb[o00 + dq + CH];
    float u2 = gb[o00 + dq + 2 * CH];

    int xo = p * 128 + q;
    float x00 = xb[xo];
    float x01 = xb[xo + cq];

    // weights for this output row: row index s+1 (warp-uniform address)
    float wA0 = wgt[(s + 1) * 5 + 1] * x00;
    float wA1 = wgt[(s + 1) * 5 + 2] * x00;
    float wA2 = wgt[(s + 1) * 5 + 3] * x00;
    float wA3 = wgt[(s + 1) * 5 + 4] * x00;
    float wCol = wgt[(s + 1) * 5] * x01;

    float espS = (s == 1) ? 1.0f : ((s == 3) ? E4 : E1);

    float ctr0[4] = {c0.x, c0.y, c0.z, c0.w};
    float ctr1[4] = {c1.x, c1.y, c1.z, c1.w};
    float ctr2[4] = {c2.x, c2.y, c2.z, c2.w};
    float wAr[4]  = {wA0, wA1, wA2, wA3};
    const float espC[4] = {E1, 1.0f, E1, E4};

    float num[4], den[4];
#pragma unroll
    for (int r = 0; r < 4; r++) {
        float d0 = t0 - ctr0[r];
        float d1 = t1 - ctr1[r];
        float d2 = t2 - ctr2[r];
        float e = __expf(-0.125f * (d0 * d0 + d1 * d1 + d2 * d2)) * (espS * espC[r]);
        den[r] = e;
        num[r] = e * wAr[r];
    }
    {   // second-col tap for r=3
        float h0 = u0 - ctr0[3];
        float h1 = u1 - ctr1[3];
        float h2 = u2 - ctr2[3];
        float e3 = __expf(-0.125f * (h0 * h0 + h1 * h1 + h2 * h2)) * (espS * E4);
        if (col2) { den[3] += e3; num[3] += e3 * wCol; }
    }

    if (s == 3) {    // warp-uniform: second-row taps
        bool row2 = (p < 127);
        int dr = row2 ? 4 * 512 : 0;
        int cp = row2 ? 1 : 0;
        float v0 = gb[o00 + dr];
        float v1 = gb[o00 + dr + CH];
        float v2 = gb[o00 + dr + 2 * CH];
        float z0 = gb[o00 + dr + dq];
        float z1 = gb[o00 + dr + dq + CH];
        float z2 = gb[o00 + dr + dq + 2 * CH];
        float x10 = xb[xo + cp * 128];
        float x11 = xb[xo + cp * 128 + cq];

        if (row2) {
#pragma unroll
            for (int r = 0; r < 4; r++) {
                float f0 = v0 - ctr0[r];
                float f1 = v1 - ctr1[r];
                float f2 = v2 - ctr2[r];
                float e2 = __expf(-0.125f * (f0 * f0 + f1 * f1 + f2 * f2)) * (E4 * espC[r]);
                den[r] += e2;
                num[r] += e2 * wgt[r + 1] * x10;
            }
            if (col2) {  // corner tap
                float k0 = z0 - ctr0[3];
                float k1 = z1 - ctr1[3];
                float k2 = z2 - ctr2[3];
                float e4 = __expf(-0.125f * (k0 * k0 + k1 * k1 + k2 * k2)) * (E4 * E4);
                den[3] += e4;
                num[3] += e4 * wgt[0] * x11;
            }
        }
    }

    float4 o = make_float4(__fdividef(num[0], den[0]),
                           __fdividef(num[1], den[1]),
                           __fdividef(num[2], den[2]),
                           __fdividef(num[3], den[3]));
    *(float4*)(out + (size_t)b * CH + hrow) = o;
}

extern "C" void kernel_launch(void* const* d_in, const int* in_sizes, int n_in,
                              void* d_out, int out_size)
{
    const float* x   = (const float*)d_in[0];
    const float* g   = (const float*)d_in[1];
    const float* wgt = (const float*)d_in[2];
    float* out = (float*)d_out;

    int total_threads = out_size / 4;     // 262144
    jb_kernel<<<total_threads / 256, 256>>>(x, g, wgt, out);
}

// round 6
// speedup vs baseline: 1.0627x; 1.0627x over previous
#include <cuda_runtime.h>
#include <cuda_bf16.h>

// JointBilateral upsample, S=4, K=5. One thread = 4 horizontal output pixels:
// output row 4p+s, cols 4q..4q+3. s is warp-uniform.
//
// MUFU-free: exp(-z) for z in [0, 0.094] via cubic Horner (err <= 3.3e-6);
// reciprocal via bit-hack + 2 Newton iterations (err ~6e-6).
//
// e(tap) = exp(-0.125*||g_tap - g_ctr||^2) * exp(-0.005*((i-2)^2+(j-2)^2))
// out = sum(e * wgt[4-i][4-j] * x_tap) / sum(e)

#define CH  (512 * 512)
#define E1  0.9950124791926823f   /* exp(-0.005) */
#define E4  0.9801986733067553f   /* exp(-0.020) */

// exp(-z), z >= 0 and small (<= ~0.1): 1 - z + z^2/2 - z^3/6
__device__ __forceinline__ float exp_neg_small(float z)
{
    float p = fmaf(-0.16666667f, z, 0.5f);
    p = fmaf(p, z, -1.0f);
    return fmaf(p, z, 1.0f);
}

// 1/x for x in ~[0.5, 8]: bit-hack seed + 2 Newton iterations
__device__ __forceinline__ float fast_rcp(float x)
{
    float r = __uint_as_float(0x7EF311C3u - __float_as_uint(x));
    r = r * fmaf(-x, r, 2.0f);
    r = r * fmaf(-x, r, 2.0f);
    return r;
}

__global__ void __launch_bounds__(256) jb_kernel(
    const float* __restrict__ x,
    const float* __restrict__ g,
    const float* __restrict__ wgt,
    float* __restrict__ out)
{
    int idx = blockIdx.x * 256 + threadIdx.x;   // 262144 threads
    int q = idx & 127;
    int s = (idx >> 7) & 3;      // warp-uniform
    int p = (idx >> 9) & 127;
    int b = idx >> 16;

    const float* gb = g + (size_t)b * 3 * CH;
    const float* xb = x + b * (128 * 128);

    bool col2 = (q < 127);
    int dq = col2 ? 4 : 0;
    int cq = col2 ? 1 : 0;

    int o00 = (4 * p + 1) * 512 + (4 * q + 1);
    int hrow = (4 * p + s) * 512 + 4 * q;

    // ---- front-loaded: centers, first tap, col tap, x ----
    float4 c0 = *(const float4*)(gb + hrow);
    float4 c1 = *(const float4*)(gb + CH + hrow);
    float4 c2 = *(const float4*)(gb + 2 * CH + hrow);

    float t0 = gb[o00];
    float t1 = gb[o00 + CH];
    float t2 = gb[o00 + 2 * CH];
    float u0 = gb[o00 + dq];
    float u1 = gb[o00 + dq + CH];
    float u2 = gb[o00 + dq + 2 * CH];

    int xo = p * 128 + q;
    float x00 = xb[xo];
    float x01 = xb[xo + cq];

    // weights for this output row: row index s+1 (warp-uniform address)
    float wA0 = wgt[(s + 1) * 5 + 1] * x00;
    float wA1 = wgt[(s + 1) * 5 + 2] * x00;
    float wA2 = wgt[(s + 1) * 5 + 3] * x00;
    float wA3 = wgt[(s + 1) * 5 + 4] * x00;
    float wCol = wgt[(s + 1) * 5] * x01;

    float espS = (s == 1) ? 1.0f : ((s == 3) ? E4 : E1);

    float ctr0[4] = {c0.x, c0.y, c0.z, c0.w};
    float ctr1[4] = {c1.x, c1.y, c1.z, c1.w};
    float ctr2[4] = {c2.x, c2.y, c2.z, c2.w};
    float wAr[4]  = {wA0, wA1, wA2, wA3};
    const float espC[4] = {E1, 1.0f, E1, E4};

    float num[4], den[4];
#pragma unroll
    for (int r = 0; r < 4; r++) {
        float d0 = t0 - ctr0[r];
        float d1 = t1 - ctr1[r];
        float d2 = t2 - ctr2[r];
        float z = 0.125f * fmaf(d0, d0, fmaf(d1, d1, d2 * d2));
        float e = exp_neg_small(z) * (espS * espC[r]);
        den[r] = e;
        num[r] = e * wAr[r];
    }
    {   // second-col tap for r=3
        float h0 = u0 - ctr0[3];
        float h1 = u1 - ctr1[3];
        float h2 = u2 - ctr2[3];
        float z = 0.125f * fmaf(h0, h0, fmaf(h1, h1, h2 * h2));
        float e3 = exp_neg_small(z) * (espS * E4);
        if (col2) { den[3] += e3; num[3] += e3 * wCol; }
    }

    if (s == 3) {    // warp-uniform: second-row taps
        bool row2 = (p < 127);
        int dr = row2 ? 4 * 512 : 0;
        int cp = row2 ? 1 : 0;
        float v0 = gb[o00 + dr];
        float v1 = gb[o00 + dr + CH];
        float v2 = gb[o00 + dr + 2 * CH];
        float z0 = gb[o00 + dr + dq];
        float z1 = gb[o00 + dr + dq + CH];
        float z2 = gb[o00 + dr + dq + 2 * CH];
        float x10 = xb[xo + cp * 128];
        float x11 = xb[xo + cp * 128 + cq];

        if (row2) {
#pragma unroll
            for (int r = 0; r < 4; r++) {
                float f0 = v0 - ctr0[r];
                float f1 = v1 - ctr1[r];
                float f2 = v2 - ctr2[r];
                float z = 0.125f * fmaf(f0, f0, fmaf(f1, f1, f2 * f2));
                float e2 = exp_neg_small(z) * (E4 * espC[r]);
                den[r] += e2;
                num[r] += e2 * wgt[r + 1] * x10;
            }
            if (col2) {  // corner tap
                float k0 = z0 - ctr0[3];
                float k1 = z1 - ctr1[3];
                float k2 = z2 - ctr2[3];
                float zz = 0.125f * fmaf(k0, k0, fmaf(k1, k1, k2 * k2));
                float e4 = exp_neg_small(zz) * (E4 * E4);
                den[3] += e4;
                num[3] += e4 * wgt[0] * x11;
            }
        }
    }

    float4 o = make_float4(num[0] * fast_rcp(den[0]),
                           num[1] * fast_rcp(den[1]),
                           num[2] * fast_rcp(den[2]),
                           num[3] * fast_rcp(den[3]));
    *(float4*)(out + (size_t)b * CH + hrow) = o;
}

extern "C" void kernel_launch(void* const* d_in, const int* in_sizes, int n_in,
                              void* d_out, int out_size)
{
    const float* x   = (const float*)d_in[0];
    const float* g   = (const float*)d_in[1];
    const float* wgt = (const float*)d_in[2];
    float* out = (float*)d_out;

    int total_threads = out_size / 4;     // 262144
    jb_kernel<<<total_threads / 256, 256>>>(x, g, wgt, out);
}